// round 11
// baseline (speedup 1.0000x reference)
#include <cuda_runtime.h>
#include <cstdint>

// BERT_CRF: B=64, S=512, H=768, L=9
//   Kernel 1 (fused): grid 512 = 64 batches x 8 chunks, block 128.
//     Per (b, c): emissions GEMM for rows [64c,64c+64) (cp.async pipelined,
//     R=2 register blocking, W broadcast from smem), emissions stay in smem
//     (aliased into sH[1] after GEMM); then 9x9 log-semiring chunk product
//     matrix (63/64 steps) + numerator partial.
//   Kernel 2 (final): grid 64 x 32 — apply 8 chunk matrices per batch,
//     per-batch loss; last-finished block folds the deterministic 64->1 sum.

#define BB 64
#define SS 512
#define HH 768
#define LL 9
#define NC 8        // chunks per batch
#define CL 64       // timesteps per chunk
#define NST2 81
#define KC 32       // k-chunk width
#define NKC 24      // 768/32
#define SHS 36      // sH row stride: 4r mod 32 tiles banks -> conflict-free LDS.128

#define LOG2E 1.4426950408889634f
#define LN2   0.6931471805599453f

__device__ float g_em0[BB * LL];
__device__ float g_P[BB * NC * NST2];
__device__ float g_numpart[BB * NC];
__device__ float g_partial[BB];
__device__ unsigned g_tick;

__device__ __forceinline__ float ex2f_(float x) {
    float y; asm("ex2.approx.ftz.f32 %0, %1;" : "=f"(y) : "f"(x)); return y;
}
__device__ __forceinline__ float lg2f_(float x) {
    float y; asm("lg2.approx.ftz.f32 %0, %1;" : "=f"(y) : "f"(x)); return y;
}
__device__ __forceinline__ void cp16(void* dst, const void* src) {
    uint32_t d = (uint32_t)__cvta_generic_to_shared(dst);
    asm volatile("cp.async.cg.shared.global [%0], [%1], 16;" :: "r"(d), "l"(src));
}
__device__ __forceinline__ void cp_commit() {
    asm volatile("cp.async.commit_group;");
}
template <int N> __device__ __forceinline__ void cp_wait() {
    asm volatile("cp.async.wait_group %0;" :: "n"(N));
}

// ---------------------------------------------------------------------------
// Kernel 1: fused emissions GEMM + chunk scan
// static smem: 27648 + 18432 + 324 + 648 + 256 = 47308 B (< 48KB limit)
// ---------------------------------------------------------------------------
__global__ __launch_bounds__(128) void fused_kernel(
    const float* __restrict__ hidden,   // [B*S, H]
    const int*   __restrict__ mask,     // [B,S]
    const int*   __restrict__ labels,   // [B,S]
    const float* __restrict__ Wm,       // [H, L]
    const float* __restrict__ bias,     // [L]
    const float* __restrict__ trans)    // [L,L]
{
    __shared__ float sW[HH * LL];          // 27648 B
    __shared__ float sH[2][CL * SHS];      // 2 x 9216 B
    __shared__ float sT[NST2];
    __shared__ float sP[2][NST2];
    __shared__ int   sMask[CL];

    // aliases valid after the GEMM mainloop (guarded by __syncthreads):
    float* sRed = &sH[0][0];               // 4*64*9 = 2304 floats = all of sH[0]
    float* sEm  = &sH[1][0];               // 64*9   = 576 floats into sH[1]

    const int tid = threadIdx.x;
    const int b = blockIdx.x >> 3;
    const int c = blockIdx.x & 7;
    const size_t row0 = (size_t)b * SS + c * CL;

    // staging map: 2 threads per row, 16 floats each
    const int srow = tid >> 1;
    const int sc   = tid & 1;
    const float* gsrc = hidden + (row0 + srow) * HH + sc * 16;

    // prologue: async-load k-chunk 0 into sH[0]
#pragma unroll
    for (int i = 0; i < 4; ++i)
        cp16(&sH[0][srow * SHS + sc * 16 + i * 4], gsrc + i * 4);
    cp_commit();

    // stage W + small tables (overlaps with cp.async in flight)
    {
        const float4* W4 = (const float4*)Wm;
        for (int i = tid; i < (HH * LL) / 4; i += 128)
            ((float4*)sW)[i] = W4[i];
    }
    if (tid < NST2) sT[tid] = trans[tid];
    if (tid < CL)   sMask[tid] = mask[b * SS + c * CL + tid];

    const int w = tid >> 5;                // warp: k-subslice [8w, 8w+8) per chunk
    const int r = tid & 31;                // lane: rows r and r+32

    float acc0[LL], acc1[LL];
#pragma unroll
    for (int l = 0; l < LL; ++l) { acc0[l] = 0.f; acc1[l] = 0.f; }

    for (int kc = 0; kc < NKC; ++kc) {
        if (kc + 1 < NKC) {
            const float* gn = gsrc + (kc + 1) * KC;
            float* dst = &sH[(kc + 1) & 1][srow * SHS + sc * 16];
#pragma unroll
            for (int i = 0; i < 4; ++i)
                cp16(dst + i * 4, gn + i * 4);
            cp_commit();
            cp_wait<1>();                  // chunk kc resident
        } else {
            cp_wait<0>();
        }
        __syncthreads();

        const float* hb = &sH[kc & 1][0];
#pragma unroll
        for (int g = 0; g < 2; ++g) {
            const int kl = w * 8 + g * 4;
            float4 h0 = *(const float4*)&hb[r * SHS + kl];
            float4 h1 = *(const float4*)&hb[(r + 32) * SHS + kl];
            const int k0 = kc * KC + kl;   // multiple of 4
            float wreg[36];
#pragma unroll
            for (int q = 0; q < 9; ++q)
                *(float4*)&wreg[q * 4] = ((const float4*)&sW[k0 * LL])[q];
#pragma unroll
            for (int s = 0; s < 4; ++s) {
                float hv0 = (s == 0) ? h0.x : (s == 1) ? h0.y : (s == 2) ? h0.z : h0.w;
                float hv1 = (s == 0) ? h1.x : (s == 1) ? h1.y : (s == 2) ? h1.z : h1.w;
#pragma unroll
                for (int l = 0; l < LL; ++l) {
                    acc0[l] = fmaf(hv0, wreg[s * LL + l], acc0[l]);
                    acc1[l] = fmaf(hv1, wreg[s * LL + l], acc1[l]);
                }
            }
        }
        __syncthreads();                   // buffer consumed before reuse
    }

    // ---- reduction across the 4 k-subslice warps (sRed = sH[0]) ----
#pragma unroll
    for (int l = 0; l < LL; ++l) {
        sRed[(w * CL + r) * LL + l]        = acc0[l];
        sRed[(w * CL + r + 32) * LL + l]   = acc1[l];
    }
    __syncthreads();

    if (tid < CL) {
#pragma unroll
        for (int l = 0; l < LL; ++l) {
            float em = bias[l];
#pragma unroll
            for (int s = 0; s < 4; ++s)
                em += sRed[(s * CL + tid) * LL + l];
            sEm[tid * LL + l] = em;         // sEm = sH[1], disjoint from sRed
        }
        if (c == 0 && tid == 0) {
#pragma unroll
            for (int l = 0; l < LL; ++l) g_em0[b * LL + l] = sEm[l];
        }
    }
    if (tid < 96) {
        int lane = tid & 31;
        int e = (tid >> 5) * 27 + lane;
        if (lane < 27) {
            int i = e / LL, j = e - i * LL;
            sP[0][e] = (i == j) ? 0.f : -1e30f;
        }
    }
    __syncthreads();

    if (tid >= 96) {
        // ---- warp 3: numerator partial (2 timesteps per lane) ----
        const int l = tid - 96;
        float v = 0.f;
        {
            const int t = c * CL + l;
            if (t >= 1 && sMask[l]) {
                int lt  = labels[b * SS + t];
                int ltp = labels[b * SS + t - 1];
                v += sT[ltp * LL + lt] + sEm[l * LL + lt];
            }
        }
        {
            const int t = c * CL + l + 32;     // always >= 32 >= 1
            if (sMask[l + 32]) {
                int lt  = labels[b * SS + t];
                int ltp = labels[b * SS + t - 1];
                v += sT[ltp * LL + lt] + sEm[(l + 32) * LL + lt];
            }
        }
#pragma unroll
        for (int o = 16; o > 0; o >>= 1) v += __shfl_xor_sync(0xffffffffu, v, o);
        if (l == 0) g_numpart[b * NC + c] = v;
    } else {
        // ---- warps 0-2: log-semiring chunk-matrix scan (base-2) ----
        const int lane = tid & 31;
        const int e = (tid >> 5) * 27 + lane;
        const bool act = (lane < 27);
        const int i = e / LL;
        const int j = e - i * LL;

        float Tcol[LL];
        if (act) {
#pragma unroll
            for (int k = 0; k < LL; ++k) Tcol[k] = sT[k * LL + j] * LOG2E;
        }

        int cur = 0;
        const int t0 = (c == 0) ? 1 : c * CL;
        const int t1 = c * CL + CL;
        for (int t = t0; t < t1; ++t) {
            if (!sMask[t - c * CL]) continue;    // block-uniform
            if (act) {
                const float* Pr = &sP[cur][i * LL];
                float x[LL];
                float mx = -1e30f;
#pragma unroll
                for (int k = 0; k < LL; ++k) {
                    x[k] = Pr[k] + Tcol[k];
                    mx = fmaxf(mx, x[k]);
                }
                float s = 0.f;
#pragma unroll
                for (int k = 0; k < LL; ++k) s += ex2f_(x[k] - mx);
                sP[cur ^ 1][e] = fmaf(sEm[(t - c * CL) * LL + j], LOG2E,
                                      mx + lg2f_(s));
            }
            asm volatile("bar.sync 1, 96;" ::: "memory");
            cur ^= 1;
        }
        if (act) g_P[((size_t)b * NC + c) * NST2 + e] = sP[cur][e];
    }
}

// ---------------------------------------------------------------------------
// Kernel 2: per-batch finalize + last-block-done deterministic reduction
// ---------------------------------------------------------------------------
__global__ __launch_bounds__(32) void crf_final_kernel(
    const int*   __restrict__ mask,
    const int*   __restrict__ labels,
    const float* __restrict__ start_t,
    const float* __restrict__ end_t,
    float*       __restrict__ out)
{
    const int b = blockIdx.x;
    const int lane = threadIdx.x;
    __shared__ float sPm[NC * NST2];

    for (int idx = lane; idx < NC * NST2; idx += 32)
        sPm[idx] = g_P[(size_t)b * NC * NST2 + idx];

    int ms = 0;
    for (int t = lane; t < SS; t += 32) ms += mask[b * SS + t];
#pragma unroll
    for (int o = 16; o > 0; o >>= 1) ms += __shfl_xor_sync(0xffffffffu, ms, o);

    float np = (lane < NC) ? g_numpart[b * NC + lane] : 0.f;
#pragma unroll
    for (int o = 16; o > 0; o >>= 1) np += __shfl_xor_sync(0xffffffffu, np, o);

    __syncwarp();

    const int jj = (lane < LL) ? lane : 0;
    float a[LL];
#pragma unroll
    for (int q = 0; q < LL; ++q)
        a[q] = LOG2E * (start_t[q] + g_em0[b * LL + q]);

    for (int cc = 0; cc < NC; ++cc) {
        float x[LL];
        float mx = -1e30f;
#pragma unroll
        for (int q = 0; q < LL; ++q) {
            x[q] = a[q] + sPm[cc * NST2 + q * LL + jj];
            mx = fmaxf(mx, x[q]);
        }
        float s = 0.f;
#pragma unroll
        for (int q = 0; q < LL; ++q) s += ex2f_(x[q] - mx);
        float pn = mx + lg2f_(s);
#pragma unroll
        for (int q = 0; q < LL; ++q) a[q] = __shfl_sync(0xffffffffu, pn, q);
    }

    float x[LL];
    float mx = -1e30f;
#pragma unroll
    for (int q = 0; q < LL; ++q) {
        x[q] = fmaf(end_t[q], LOG2E, a[q]);
        mx = fmaxf(mx, x[q]);
    }
    float s = 0.f;
#pragma unroll
    for (int q = 0; q < LL; ++q) s += ex2f_(x[q] - mx);
    float denom = LN2 * (mx + lg2f_(s));

    if (lane == 0) {
        int last = ms - 1;
        int lab0 = labels[b * SS];
        int labL = labels[b * SS + last];
        float num = start_t[lab0] + g_em0[b * LL + lab0] + np + end_t[labL];
        g_partial[b] = denom - num;
    }
    __threadfence();

    unsigned tk = 0;
    if (lane == 0) tk = atomicAdd(&g_tick, 1u);
    tk = __shfl_sync(0xffffffffu, tk, 0);
    if (tk == BB - 1) {
        // last block: fixed-order deterministic 64 -> 1 sum
        float v = g_partial[lane] + g_partial[lane + 32];
#pragma unroll
        for (int o = 16; o > 0; o >>= 1) v += __shfl_xor_sync(0xffffffffu, v, o);
        if (lane == 0) {
            out[0] = v;
            g_tick = 0;     // reset for next (graph-replayed) call
        }
    }
}

// ---------------------------------------------------------------------------
extern "C" void kernel_launch(void* const* d_in, const int* in_sizes, int n_in,
                              void* d_out, int out_size)
{
    (void)in_sizes; (void)n_in; (void)out_size;
    const float* hidden  = (const float*)d_in[0];
    const int*   mask    = (const int*)  d_in[1];
    const int*   labels  = (const int*)  d_in[2];
    const float* Wm      = (const float*)d_in[3];
    const float* bias    = (const float*)d_in[4];
    const float* start_t = (const float*)d_in[5];
    const float* end_t   = (const float*)d_in[6];
    const float* trans   = (const float*)d_in[7];

    fused_kernel<<<BB * NC, 128>>>(hidden, mask, labels, Wm, bias, trans);
    crf_final_kernel<<<BB, 32>>>(mask, labels, start_t, end_t, (float*)d_out);
}

// round 12
// speedup vs baseline: 1.0512x; 1.0512x over previous
#include <cuda_runtime.h>
#include <cstdint>

// BERT_CRF: B=64, S=512, H=768, L=9 — single-kernel version.
//   grid 512 = 64 batches x 8 chunks, block 128.
//   Per (b, c): emissions GEMM for rows [64c,64c+64) (cp.async pipelined,
//   R=2 register blocking, W broadcast from smem), emissions stay in smem;
//   then 9x9 log-semiring chunk product matrix + numerator partial.
//   Tail: per-batch ticket — last chunk-block of batch b runs the 8-apply
//   finalize in warp 0; global ticket folds the deterministic 64->1 sum.

#define BB 64
#define SS 512
#define HH 768
#define LL 9
#define NC 8        // chunks per batch
#define CL 64       // timesteps per chunk
#define NST2 81
#define KC 32       // k-chunk width
#define NKC 24      // 768/32
#define SHS 36      // sH row stride: 4r mod 32 tiles banks -> conflict-free LDS.128

#define LOG2E 1.4426950408889634f
#define LN2   0.6931471805599453f

__device__ float g_em0[BB * LL];
__device__ float g_P[BB * NC * NST2];
__device__ float g_numpart[BB * NC];
__device__ float g_partial[BB];
__device__ unsigned g_bt[BB];     // per-batch tickets
__device__ unsigned g_tick;       // global ticket

__device__ __forceinline__ float ex2f_(float x) {
    float y; asm("ex2.approx.ftz.f32 %0, %1;" : "=f"(y) : "f"(x)); return y;
}
__device__ __forceinline__ float lg2f_(float x) {
    float y; asm("lg2.approx.ftz.f32 %0, %1;" : "=f"(y) : "f"(x)); return y;
}
__device__ __forceinline__ void cp16(void* dst, const void* src) {
    uint32_t d = (uint32_t)__cvta_generic_to_shared(dst);
    asm volatile("cp.async.cg.shared.global [%0], [%1], 16;" :: "r"(d), "l"(src));
}
__device__ __forceinline__ void cp_commit() {
    asm volatile("cp.async.commit_group;");
}
template <int N> __device__ __forceinline__ void cp_wait() {
    asm volatile("cp.async.wait_group %0;" :: "n"(N));
}

// ---------------------------------------------------------------------------
__global__ __launch_bounds__(128) void fused_kernel(
    const float* __restrict__ hidden,   // [B*S, H]
    const int*   __restrict__ mask,     // [B,S]
    const int*   __restrict__ labels,   // [B,S]
    const float* __restrict__ Wm,       // [H, L]
    const float* __restrict__ bias,     // [L]
    const float* __restrict__ trans,    // [L,L]
    const float* __restrict__ start_t,  // [L]
    const float* __restrict__ end_t,    // [L]
    float*       __restrict__ out)      // [1]
{
    __shared__ float sW[HH * LL];          // 27648 B
    __shared__ float sH[2][CL * SHS];      // 2 x 9216 B
    __shared__ float sT[NST2];
    __shared__ float sP[2][NST2];
    __shared__ int   sMask[CL];
    __shared__ unsigned s_tk;

    // aliases valid after the GEMM mainloop (guarded by __syncthreads):
    float* sRed = &sH[0][0];               // 4*64*9 = 2304 floats = all of sH[0]
    float* sEm  = &sH[1][0];               // 64*9   = 576 floats into sH[1]

    const int tid = threadIdx.x;
    const int b = blockIdx.x >> 3;
    const int c = blockIdx.x & 7;
    const size_t row0 = (size_t)b * SS + c * CL;

    // staging map: 2 threads per row, 16 floats each
    const int srow = tid >> 1;
    const int sc   = tid & 1;
    const float* gsrc = hidden + (row0 + srow) * HH + sc * 16;

    // prologue: async-load k-chunk 0 into sH[0]
#pragma unroll
    for (int i = 0; i < 4; ++i)
        cp16(&sH[0][srow * SHS + sc * 16 + i * 4], gsrc + i * 4);
    cp_commit();

    // stage W + small tables (overlaps with cp.async in flight)
    {
        const float4* W4 = (const float4*)Wm;
        for (int i = tid; i < (HH * LL) / 4; i += 128)
            ((float4*)sW)[i] = W4[i];
    }
    if (tid < NST2) sT[tid] = trans[tid];
    if (tid < CL)   sMask[tid] = mask[b * SS + c * CL + tid];

    const int w = tid >> 5;                // warp: k-subslice [8w, 8w+8) per chunk
    const int r = tid & 31;                // lane: rows r and r+32

    float acc0[LL], acc1[LL];
#pragma unroll
    for (int l = 0; l < LL; ++l) { acc0[l] = 0.f; acc1[l] = 0.f; }

    for (int kc = 0; kc < NKC; ++kc) {
        if (kc + 1 < NKC) {
            const float* gn = gsrc + (kc + 1) * KC;
            float* dst = &sH[(kc + 1) & 1][srow * SHS + sc * 16];
#pragma unroll
            for (int i = 0; i < 4; ++i)
                cp16(dst + i * 4, gn + i * 4);
            cp_commit();
            cp_wait<1>();                  // chunk kc resident
        } else {
            cp_wait<0>();
        }
        __syncthreads();

        const float* hb = &sH[kc & 1][0];
#pragma unroll
        for (int g = 0; g < 2; ++g) {
            const int kl = w * 8 + g * 4;
            float4 h0 = *(const float4*)&hb[r * SHS + kl];
            float4 h1 = *(const float4*)&hb[(r + 32) * SHS + kl];
            const int k0 = kc * KC + kl;   // multiple of 4
            float wreg[36];
#pragma unroll
            for (int q = 0; q < 9; ++q)
                *(float4*)&wreg[q * 4] = ((const float4*)&sW[k0 * LL])[q];
#pragma unroll
            for (int s = 0; s < 4; ++s) {
                float hv0 = (s == 0) ? h0.x : (s == 1) ? h0.y : (s == 2) ? h0.z : h0.w;
                float hv1 = (s == 0) ? h1.x : (s == 1) ? h1.y : (s == 2) ? h1.z : h1.w;
#pragma unroll
                for (int l = 0; l < LL; ++l) {
                    acc0[l] = fmaf(hv0, wreg[s * LL + l], acc0[l]);
                    acc1[l] = fmaf(hv1, wreg[s * LL + l], acc1[l]);
                }
            }
        }
        __syncthreads();                   // buffer consumed before reuse
    }

    // ---- reduction across the 4 k-subslice warps (sRed = sH[0]) ----
#pragma unroll
    for (int l = 0; l < LL; ++l) {
        sRed[(w * CL + r) * LL + l]        = acc0[l];
        sRed[(w * CL + r + 32) * LL + l]   = acc1[l];
    }
    __syncthreads();

    if (tid < CL) {
#pragma unroll
        for (int l = 0; l < LL; ++l) {
            float em = bias[l];
#pragma unroll
            for (int s = 0; s < 4; ++s)
                em += sRed[(s * CL + tid) * LL + l];
            sEm[tid * LL + l] = em;         // sEm = sH[1], disjoint from sRed
        }
        if (c == 0 && tid == 0) {
#pragma unroll
            for (int l = 0; l < LL; ++l) g_em0[b * LL + l] = sEm[l];
        }
    }
    if (tid < 96) {
        int lane = tid & 31;
        int e = (tid >> 5) * 27 + lane;
        if (lane < 27) {
            int i = e / LL, j = e - i * LL;
            sP[0][e] = (i == j) ? 0.f : -1e30f;
        }
    }
    __syncthreads();

    if (tid >= 96) {
        // ---- warp 3: numerator partial (2 timesteps per lane) ----
        const int l = tid - 96;
        float v = 0.f;
        {
            const int t = c * CL + l;
            if (t >= 1 && sMask[l]) {
                int lt  = labels[b * SS + t];
                int ltp = labels[b * SS + t - 1];
                v += sT[ltp * LL + lt] + sEm[l * LL + lt];
            }
        }
        {
            const int t = c * CL + l + 32;     // always >= 32 >= 1
            if (sMask[l + 32]) {
                int lt  = labels[b * SS + t];
                int ltp = labels[b * SS + t - 1];
                v += sT[ltp * LL + lt] + sEm[(l + 32) * LL + lt];
            }
        }
#pragma unroll
        for (int o = 16; o > 0; o >>= 1) v += __shfl_xor_sync(0xffffffffu, v, o);
        if (l == 0) g_numpart[b * NC + c] = v;
    } else {
        // ---- warps 0-2: log-semiring chunk-matrix scan (base-2) ----
        const int lane = tid & 31;
        const int e = (tid >> 5) * 27 + lane;
        const bool act = (lane < 27);
        const int i = e / LL;
        const int j = e - i * LL;

        float Tcol[LL];
        if (act) {
#pragma unroll
            for (int k = 0; k < LL; ++k) Tcol[k] = sT[k * LL + j] * LOG2E;
        }

        int cur = 0;
        const int t0 = (c == 0) ? 1 : c * CL;
        const int t1 = c * CL + CL;
        for (int t = t0; t < t1; ++t) {
            if (!sMask[t - c * CL]) continue;    // block-uniform
            if (act) {
                const float* Pr = &sP[cur][i * LL];
                float x[LL];
                float mx = -1e30f;
#pragma unroll
                for (int k = 0; k < LL; ++k) {
                    x[k] = Pr[k] + Tcol[k];
                    mx = fmaxf(mx, x[k]);
                }
                float s = 0.f;
#pragma unroll
                for (int k = 0; k < LL; ++k) s += ex2f_(x[k] - mx);
                sP[cur ^ 1][e] = fmaf(sEm[(t - c * CL) * LL + j], LOG2E,
                                      mx + lg2f_(s));
            }
            asm volatile("bar.sync 1, 96;" ::: "memory");
            cur ^= 1;
        }
        if (act) g_P[((size_t)b * NC + c) * NST2 + e] = sP[cur][e];
    }

    // ================= tail: per-batch ticket + finalize =================
    __threadfence();        // each thread's global writes visible chip-wide
    __syncthreads();        // all threads' fences complete before the ticket
    if (tid == 0) s_tk = atomicAdd(&g_bt[b], 1u);
    __syncthreads();
    if (s_tk != NC - 1) return;    // not the last chunk-block of batch b

    // Last block of batch b: warp 0 finalizes; other warps exit.
    if (tid >= 32) return;
    const int lane = tid;
    __threadfence();               // acquire-ish: order reads after ticket

    // chunk matrices for batch b -> smem (sH[0] free: 648 floats)
    float* sPm = &sH[0][0];
    for (int idx = lane; idx < NC * NST2; idx += 32)
        sPm[idx] = g_P[(size_t)b * NC * NST2 + idx];

    int ms = 0;
    for (int t = lane; t < SS; t += 32) ms += mask[b * SS + t];
#pragma unroll
    for (int o = 16; o > 0; o >>= 1) ms += __shfl_xor_sync(0xffffffffu, ms, o);

    float np = (lane < NC) ? g_numpart[b * NC + lane] : 0.f;
#pragma unroll
    for (int o = 16; o > 0; o >>= 1) np += __shfl_xor_sync(0xffffffffu, np, o);

    __syncwarp();

    const int jj = (lane < LL) ? lane : 0;
    float a[LL];
#pragma unroll
    for (int q = 0; q < LL; ++q)
        a[q] = LOG2E * (start_t[q] + g_em0[b * LL + q]);

    for (int cc = 0; cc < NC; ++cc) {
        float x[LL];
        float mx = -1e30f;
#pragma unroll
        for (int q = 0; q < LL; ++q) {
            x[q] = a[q] + sPm[cc * NST2 + q * LL + jj];
            mx = fmaxf(mx, x[q]);
        }
        float s = 0.f;
#pragma unroll
        for (int q = 0; q < LL; ++q) s += ex2f_(x[q] - mx);
        float pn = mx + lg2f_(s);
#pragma unroll
        for (int q = 0; q < LL; ++q) a[q] = __shfl_sync(0xffffffffu, pn, q);
    }

    float x[LL];
    float mx = -1e30f;
#pragma unroll
    for (int q = 0; q < LL; ++q) {
        x[q] = fmaf(end_t[q], LOG2E, a[q]);
        mx = fmaxf(mx, x[q]);
    }
    float s = 0.f;
#pragma unroll
    for (int q = 0; q < LL; ++q) s += ex2f_(x[q] - mx);
    float denom = LN2 * (mx + lg2f_(s));

    if (lane == 0) {
        int last = ms - 1;
        int lab0 = labels[b * SS];
        int labL = labels[b * SS + last];
        float num = start_t[lab0] + g_em0[b * LL + lab0] + np + end_t[labL];
        g_partial[b] = denom - num;
        g_bt[b] = 0;               // reset per-batch ticket for graph replay
    }
    __threadfence();

    unsigned gt = 0;
    if (lane == 0) gt = atomicAdd(&g_tick, 1u);
    gt = __shfl_sync(0xffffffffu, gt, 0);
    if (gt == BB - 1) {
        // last batch finalizer: fixed-order deterministic 64 -> 1 sum
        float v = g_partial[lane] + g_partial[lane + 32];
#pragma unroll
        for (int o = 16; o > 0; o >>= 1) v += __shfl_xor_sync(0xffffffffu, v, o);
        if (lane == 0) {
            out[0] = v;
            g_tick = 0;            // reset global ticket for graph replay
        }
    }
}

// ---------------------------------------------------------------------------
extern "C" void kernel_launch(void* const* d_in, const int* in_sizes, int n_in,
                              void* d_out, int out_size)
{
    (void)in_sizes; (void)n_in; (void)out_size;
    const float* hidden  = (const float*)d_in[0];
    const int*   mask    = (const int*)  d_in[1];
    const int*   labels  = (const int*)  d_in[2];
    const float* Wm      = (const float*)d_in[3];
    const float* bias    = (const float*)d_in[4];
    const float* start_t = (const float*)d_in[5];
    const float* end_t   = (const float*)d_in[6];
    const float* trans   = (const float*)d_in[7];

    fused_kernel<<<BB * NC, 128>>>(hidden, mask, labels, Wm, bias, trans,
                                   start_t, end_t, (float*)d_out);
}